// round 7
// baseline (speedup 1.0000x reference)
#include <cuda_runtime.h>
#include <cuda_bf16.h>
#include <stdint.h>
#include <math.h>

#define TT 256
#define BB 128
#define EE 512
#define HH 1024
#define G3 3072
#define KC 64            // K per stage (bf16 elems)
#define NSTG 48          // 3 passes * (1024/64)
#define SA 144           // smem row stride bytes (64 bf16 = 128B + 16B pad)

// per-stage smem frame (bytes)
#define OFF_AH 0
#define OFF_AI 9216      // 64*144
#define OFF_B  18432     // l0: 96 rows (13824B); l1: BH 48 rows (6912B)
#define OFF_BI 25344     // l1 only: 48 rows (6912B)
#define STG    32256
#define SMEM_DYN (3*STG) // 96768 bytes, 3-deep pipeline

// ---------------- device scratch (bss) ----------------
__device__ float g_GI0[(size_t)TT * BB * G3];
__device__ float g_h0f[2][BB * HH];
__device__ float g_h1f[2][BB * HH];
__device__ __nv_bfloat16 g_h0hi[2][BB*HH], g_h0lo[2][BB*HH];
__device__ __nv_bfloat16 g_h1hi[2][BB*HH], g_h1lo[2][BB*HH];
__device__ __nv_bfloat16 g_x1hi[2][BB*HH], g_x1lo[2][BB*HH];
__device__ __nv_bfloat16 g_Whi[3][(size_t)G3*HH];   // 0=Whh0 1=Wih1 2=Whh1
__device__ __nv_bfloat16 g_Wlo[3][(size_t)G3*HH];

// ---------------- helpers ----------------
__device__ __forceinline__ void cpa16(uint32_t dst, const void* src){
    asm volatile("cp.async.cg.shared.global [%0], [%1], 16;" :: "r"(dst), "l"(src));
}
__device__ __forceinline__ void cpa_commit(){ asm volatile("cp.async.commit_group;"); }
__device__ __forceinline__ void cpa_wait1(){ asm volatile("cp.async.wait_group 1;"); }

__device__ __forceinline__ void ldsm4(uint32_t* r, uint32_t a){
    asm volatile("ldmatrix.sync.aligned.m8n8.x4.shared.b16 {%0,%1,%2,%3}, [%4];"
        : "=r"(r[0]),"=r"(r[1]),"=r"(r[2]),"=r"(r[3]) : "r"(a));
}

#define MMA16816(c, a, b0, b1) \
    asm volatile("mma.sync.aligned.m16n8k16.row.col.f32.bf16.bf16.f32 " \
        "{%0,%1,%2,%3},{%4,%5,%6,%7},{%8,%9},{%0,%1,%2,%3};" \
        : "+f"((c)[0]),"+f"((c)[1]),"+f"((c)[2]),"+f"((c)[3]) \
        : "r"((a)[0]),"r"((a)[1]),"r"((a)[2]),"r"((a)[3]),"r"(b0),"r"(b1))

__device__ __forceinline__ float sigf(float v){ return 1.f/(1.f+__expf(-v)); }
__device__ __forceinline__ void split2(float v, __nv_bfloat16& hi, __nv_bfloat16& lo){
    hi = __float2bfloat16(v);
    lo = __float2bfloat16(v - __bfloat162float(hi));
}

// ---------------- init kernels ----------------
__global__ void zero_h_kernel() {
    int i = blockIdx.x*256 + threadIdx.x;  // grid 512 -> 131072 = BB*HH
    g_h0f[0][i]=0.f; g_h1f[0][i]=0.f;
    __nv_bfloat16 z = __float2bfloat16(0.f);
    g_h0hi[0][i]=z; g_h0lo[0][i]=z; g_h1hi[0][i]=z; g_h1lo[0][i]=z;
}
__global__ void split_w_kernel(const float* __restrict__ w0, const float* __restrict__ w1,
                               const float* __restrict__ w2) {
    size_t i = (size_t)blockIdx.x*256 + threadIdx.x;
    int m = blockIdx.y;
    const float* s = (m==0)? w0 : (m==1)? w1 : w2;
    __nv_bfloat16 hi, lo; split2(s[i], hi, lo);
    g_Whi[m][i]=hi; g_Wlo[m][i]=lo;
}

// ---------------- GI0 precompute (fp32, off critical path) ----------------
__global__ __launch_bounds__(256) void gi0_kernel(
    const float* __restrict__ x, const float* __restrict__ W,
    const float* __restrict__ bias, const int* __restrict__ bs)
{
    __shared__ __align__(16) float As[32][68];
    __shared__ __align__(16) float Bs[32][68];
    const int nbase = blockIdx.x * 64;
    const int trow = blockIdx.y;
    const int t = trow>>1, mb = (trow&1)<<6;
    if (mb >= bs[t]) return;
    const int tid = threadIdx.x, tx = tid&15, ty = tid>>4;
    float acc[4][4];
#pragma unroll
    for (int i=0;i<4;i++)
#pragma unroll
        for (int j=0;j<4;j++) acc[i][j]=0.f;
    const float* Arow = x + (size_t)(t*BB+mb)*EE;
    for (int k0=0;k0<EE;k0+=32) {
#pragma unroll
        for (int r=0;r<2;r++){
            int idx=tid+r*256, m=idx>>3, c4=(idx&7)*4;
            float4 v = *(const float4*)&Arow[(size_t)m*EE+k0+c4];
            As[c4][m]=v.x; As[c4+1][m]=v.y; As[c4+2][m]=v.z; As[c4+3][m]=v.w;
        }
#pragma unroll
        for (int r=0;r<2;r++){
            int idx=tid+r*256, n=idx>>3, c4=(idx&7)*4;
            float4 v = *(const float4*)&W[(size_t)(nbase+n)*EE+k0+c4];
            Bs[c4][n]=v.x; Bs[c4+1][n]=v.y; Bs[c4+2][n]=v.z; Bs[c4+3][n]=v.w;
        }
        __syncthreads();
#pragma unroll
        for (int k=0;k<32;k++){
            float4 a=*(const float4*)&As[k][tx*4];
            float4 b=*(const float4*)&Bs[k][ty*4];
            const float *ap=(const float*)&a, *bp=(const float*)&b;
#pragma unroll
            for (int i=0;i<4;i++)
#pragma unroll
                for (int j=0;j<4;j++) acc[i][j]=fmaf(ap[i],bp[j],acc[i][j]);
        }
        __syncthreads();
    }
    const int n = nbase + ty*4;
    float4 bv = *(const float4*)&bias[n];
#pragma unroll
    for (int i=0;i<4;i++){
        size_t row = (size_t)(t*BB+mb+tx*4+i);
        float4 o; o.x=acc[i][0]+bv.x; o.y=acc[i][1]+bv.y; o.z=acc[i][2]+bv.z; o.w=acc[i][3]+bv.w;
        *(float4*)&g_GI0[row*G3+n] = o;
    }
}

// ---------------- mma.sync fused step (single wave, 192 CTAs) ----------------
// CTAs [0,64):   layer0 @ t=kk : M64 x 32 hidden cols (96 gate rows, 12 n-tiles)
// CTAs [64,192): layer1 @ t=kk-1 : M64 x 16 hidden cols, dual GEMMs (6 nt each)
__global__ __launch_bounds__(128) void mma_step(
    const float* __restrict__ bhh0, const float* __restrict__ bih1,
    const float* __restrict__ bhh1, const int* __restrict__ bs, int kk)
{
    extern __shared__ __align__(16) char smem[];
    const int cta = blockIdx.x;
    const bool l1 = cta >= 64;
    const int t = l1 ? kk-1 : kk;
    if (t < 0 || t >= TT) return;
    const int p = t & 1;
    const int idx = l1 ? cta-64 : cta;
    const int jbase = l1 ? (idx>>1)*16 : (idx>>1)*32;
    const int mbase = (idx&1)*64;
    const int tid = threadIdx.x, wid = tid>>5, lane = tid&31;
    const int l4 = lane>>2, lm4 = lane&3;
    const int active = bs[t];
    const int NCOL = l1 ? 16 : 32;
    const int NT = NCOL/8;               // n-subtiles per gate (2 or 4)

    const float* hpf_all = l1 ? g_h1f[p] : g_h0f[p];
    float* hnf_all = l1 ? g_h1f[p^1] : g_h0f[p^1];
    __nv_bfloat16* hhi_all = l1 ? g_h1hi[p^1] : g_h0hi[p^1];
    __nv_bfloat16* hlo_all = l1 ? g_h1lo[p^1] : g_h0lo[p^1];

    if (mbase >= active) {
        // inactive tile: pass h through (fp32 + splits); x1 garbage rows masked later
        const int tot = 64*NCOL;
        for (int i = tid; i < tot; i += 128) {
            int r = i / NCOL, c = i % NCOL;
            size_t off = (size_t)(mbase + r)*HH + jbase + c;
            float hv = hpf_all[off];
            hnf_all[off] = hv;
            __nv_bfloat16 hi, lo; split2(hv, hi, lo);
            hhi_all[off] = hi; hlo_all[off] = lo;
        }
        return;
    }

    // pass pointer tables
    const __nv_bfloat16 *Ah[3], *Wh[3], *Ai[3], *Wi[3];
    if (!l1) {
        Ah[0]=g_h0hi[p]; Ah[1]=g_h0hi[p]; Ah[2]=g_h0lo[p];
        Wh[0]=g_Whi[0];  Wh[1]=g_Wlo[0];  Wh[2]=g_Whi[0];
    } else {
        Ah[0]=g_h1hi[p]; Ah[1]=g_h1hi[p]; Ah[2]=g_h1lo[p];
        Wh[0]=g_Whi[2];  Wh[1]=g_Wlo[2];  Wh[2]=g_Whi[2];
        Ai[0]=g_x1hi[p]; Ai[1]=g_x1hi[p]; Ai[2]=g_x1lo[p];
        Wi[0]=g_Whi[1];  Wi[1]=g_Wlo[1];  Wi[2]=g_Whi[1];
    }

    const uint32_t smem_u = (uint32_t)__cvta_generic_to_shared(smem);

    // ---- stage loader (cp.async 16B each) ----
    auto load_stage = [&](int s){
        const int pass = s >> 4;
        const int k0 = (s & 15) * KC;
        const uint32_t st = smem_u + (s % 3) * STG;
        {   // A_h: 64 rows x 8 chunks = 512 ops
            const __nv_bfloat16* A = Ah[pass];
#pragma unroll
            for (int i = 0; i < 4; i++) {
                int cid = tid + i*128, r = cid>>3, c = cid&7;
                cpa16(st + OFF_AH + r*SA + c*16, A + (size_t)(mbase+r)*HH + k0 + c*8);
            }
        }
        if (!l1) {
            // B_h: 96 rows (3 gates x 32) x 8 = 768 ops
            const __nv_bfloat16* W = Wh[pass];
#pragma unroll
            for (int i = 0; i < 6; i++) {
                int cid = tid + i*128, r = cid>>3, c = cid&7;
                int wrow = (r>>5)*HH + jbase + (r&31);
                cpa16(st + OFF_B + r*SA + c*16, W + (size_t)wrow*HH + k0 + c*8);
            }
        } else {
            const __nv_bfloat16* A = Ai[pass];
#pragma unroll
            for (int i = 0; i < 4; i++) {
                int cid = tid + i*128, r = cid>>3, c = cid&7;
                cpa16(st + OFF_AI + r*SA + c*16, A + (size_t)(mbase+r)*HH + k0 + c*8);
            }
            // B_h, B_i: 48 rows (3 gates x 16) x 8 = 384 ops each
#pragma unroll
            for (int i = 0; i < 3; i++) {
                int cid = tid + i*128, r = cid>>3, c = cid&7;
                int wrow = (r>>4)*HH + jbase + (r&15);
                cpa16(st + OFF_B  + r*SA + c*16, Wh[pass] + (size_t)wrow*HH + k0 + c*8);
                cpa16(st + OFF_BI + r*SA + c*16, Wi[pass] + (size_t)wrow*HH + k0 + c*8);
            }
        }
    };

    // accumulators: l0 ch[12]; l1 ch[6]+ci[6]
    float ch[12][4], ci[6][4];
#pragma unroll
    for (int i=0;i<12;i++)
#pragma unroll
        for (int j=0;j<4;j++) ch[i][j]=0.f;
#pragma unroll
    for (int i=0;i<6;i++)
#pragma unroll
        for (int j=0;j<4;j++) ci[i][j]=0.f;

    // ldmatrix lane address offsets
    const uint32_t a_off = (uint32_t)((wid*16 + (lane&15))*SA + (lane>>4)*16);
    const uint32_t b_off = (uint32_t)(((lane&7) + ((lane>>4)&1)*8)*SA + ((lane>>3)&1)*16);

    // 3-deep pipeline: one barrier per stage
    load_stage(0); cpa_commit();
    load_stage(1); cpa_commit();
    for (int s = 0; s < NSTG; s++) {
        cpa_wait1();
        __syncthreads();
        const uint32_t st = smem_u + (s % 3) * STG;
        const uint32_t aH = st + OFF_AH + a_off;
        const uint32_t bB = st + OFF_B  + b_off;
        if (!l1) {
#pragma unroll
            for (int kc = 0; kc < 4; kc++) {
                uint32_t a[4]; ldsm4(a, aH + kc*32);
#pragma unroll
                for (int ntp = 0; ntp < 6; ntp++) {
                    uint32_t b[4]; ldsm4(b, bB + ntp*16*SA + kc*32);
                    MMA16816(ch[2*ntp],   a, b[0], b[1]);
                    MMA16816(ch[2*ntp+1], a, b[2], b[3]);
                }
            }
        } else {
            const uint32_t aI = st + OFF_AI + a_off;
            const uint32_t bI = st + OFF_BI + b_off;
#pragma unroll
            for (int kc = 0; kc < 4; kc++) {
                uint32_t a[4], ai[4];
                ldsm4(a,  aH + kc*32);
                ldsm4(ai, aI + kc*32);
#pragma unroll
                for (int ntp = 0; ntp < 3; ntp++) {
                    uint32_t b[4];
                    ldsm4(b, bB + ntp*16*SA + kc*32);
                    MMA16816(ch[2*ntp],   a, b[0], b[1]);
                    MMA16816(ch[2*ntp+1], a, b[2], b[3]);
                    ldsm4(b, bI + ntp*16*SA + kc*32);
                    MMA16816(ci[2*ntp],   ai, b[0], b[1]);
                    MMA16816(ci[2*ntp+1], ai, b[2], b[3]);
                }
            }
        }
        if (s+2 < NSTG) load_stage(s+2);
        cpa_commit();   // empty commits at tail keep wait-count aligned
    }

    // ---- epilogue: gate math + state update ----
    const int m0 = mbase + wid*16 + l4;
    const float* bh = l1 ? bhh1 : bhh0;
#pragma unroll
    for (int c = 0; c < 4; c++) {
        if (c >= NT) break;
        const int j = jbase + c*8 + lm4*2;
        float2 bhr = *(const float2*)(bh + j);
        float2 bhz = *(const float2*)(bh + HH + j);
        float2 bhn = *(const float2*)(bh + 2*HH + j);
        float2 bir, biz, bin;
        if (l1) {
            bir = *(const float2*)(bih1 + j);
            biz = *(const float2*)(bih1 + HH + j);
            bin = *(const float2*)(bih1 + 2*HH + j);
        }
        const int rg = c, zg = NT + c, ng = 2*NT + c;
#pragma unroll
        for (int rr = 0; rr < 2; rr++) {
            const int m = m0 + rr*8;
            const bool keep = m < active;
            float gr0,gr1,gz0,gz1,gn0,gn1;
            if (!l1) {
                const float* gp = g_GI0 + (size_t)(t*BB + m)*G3;
                float2 a = *(const float2*)(gp + j);
                float2 b = *(const float2*)(gp + HH + j);
                float2 cc = *(const float2*)(gp + 2*HH + j);
                gr0=a.x; gr1=a.y; gz0=b.x; gz1=b.y; gn0=cc.x; gn1=cc.y;
            } else {
                gr0 = ci[rg][rr*2] + bir.x;  gr1 = ci[rg][rr*2+1] + bir.y;
                gz0 = ci[zg][rr*2] + biz.x;  gz1 = ci[zg][rr*2+1] + biz.y;
                gn0 = ci[ng][rr*2] + bin.x;  gn1 = ci[ng][rr*2+1] + bin.y;
            }
            float hr0 = ch[rg][rr*2] + bhr.x, hr1 = ch[rg][rr*2+1] + bhr.y;
            float hz0 = ch[zg][rr*2] + bhz.x, hz1 = ch[zg][rr*2+1] + bhz.y;
            float hn0 = ch[ng][rr*2] + bhn.x, hn1 = ch[ng][rr*2+1] + bhn.y;

            size_t off = (size_t)m*HH + j;
            float2 hp = *(const float2*)(hpf_all + off);

            float r0 = sigf(gr0+hr0), z0 = sigf(gz0+hz0);
            float nv0 = tanhf(fmaf(r0, hn0, gn0));
            float hv0 = fmaf(z0, hp.x - nv0, nv0);
            float r1 = sigf(gr1+hr1), z1 = sigf(gz1+hz1);
            float nv1 = tanhf(fmaf(r1, hn1, gn1));
            float hv1 = fmaf(z1, hp.y - nv1, nv1);

            float kv0 = keep ? hv0 : hp.x;
            float kv1 = keep ? hv1 : hp.y;

            float2 outv; outv.x = kv0; outv.y = kv1;
            *(float2*)(hnf_all + off) = outv;
            __nv_bfloat162 vhi, vlo;
            split2(kv0, vhi.x, vlo.x);
            split2(kv1, vhi.y, vlo.y);
            *(__nv_bfloat162*)(hhi_all + off) = vhi;
            *(__nv_bfloat162*)(hlo_all + off) = vlo;
            if (!l1) {
                // layer1 input = UNMASKED hn
                __nv_bfloat162 xh, xl;
                split2(hv0, xh.x, xl.x);
                split2(hv1, xh.y, xl.y);
                *(__nv_bfloat162*)(g_x1hi[p] + off) = xh;
                *(__nv_bfloat162*)(g_x1lo[p] + off) = xl;
            }
        }
    }
}

// ---------------- final gather ----------------
__global__ void gather_kernel(const int* __restrict__ u, float* __restrict__ out) {
    int idx = blockIdx.x*blockDim.x + threadIdx.x;
    int l = idx / (BB*(HH/4));
    int rem = idx % (BB*(HH/4));
    int b = rem / (HH/4), j4 = rem % (HH/4);
    const float* src = (l ? g_h1f[0] : g_h0f[0]) + (size_t)u[b]*HH;
    ((float4*)out)[idx] = ((const float4*)src)[j4];
}

// ---------------------------------------------------------------------------
extern "C" void kernel_launch(void* const* d_in, const int* in_sizes, int n_in,
                              void* d_out, int out_size) {
    const float* x    = (const float*)d_in[0];
    const float* Wih0 = (const float*)d_in[1];
    const float* Whh0 = (const float*)d_in[2];
    const float* bih0 = (const float*)d_in[3];
    const float* bhh0 = (const float*)d_in[4];
    const float* Wih1 = (const float*)d_in[5];
    const float* Whh1 = (const float*)d_in[6];
    const float* bih1 = (const float*)d_in[7];
    const float* bhh1 = (const float*)d_in[8];
    const int*   bs   = (const int*)d_in[9];
    const int*   ui   = (const int*)d_in[10];

    // idempotent, deterministic host-side attribute set (not a stream op)
    cudaFuncSetAttribute(mma_step, cudaFuncAttributeMaxDynamicSharedMemorySize, SMEM_DYN);

    zero_h_kernel<<<512, 256>>>();
    split_w_kernel<<<dim3((G3*HH)/256, 3), 256>>>(Whh0, Wih1, Whh1);
    gi0_kernel<<<dim3(48, 2*TT), 256>>>(x, Wih0, bih0, bs);
    for (int k = 0; k <= TT; k++)
        mma_step<<<192, 128, SMEM_DYN>>>(bhh0, bih1, bhh1, bs, k);
    gather_kernel<<<256, 256>>>(ui, (float*)d_out);
}

// round 8
// speedup vs baseline: 1.3672x; 1.3672x over previous
#include <cuda_runtime.h>
#include <cuda_bf16.h>
#include <stdint.h>
#include <math.h>

#define TT 256
#define BB 128
#define EE 512
#define HH 1024
#define G3 3072
#define KC 32            // K per stage
#define NSTG 96          // 3 passes * 32 chunks
#define SA 80            // smem row stride bytes (32 bf16 = 64B + 16B pad)

// per-stage smem frame (bytes)
#define OFF_A  0         // 64 rows  (5120B)
#define OFF_AI 5120      // 64 rows  (l1 only)
#define OFF_B  10240     // 48 rows  (3840B)
#define FRAME  14080
#define DEPTH  5
#define SMEM_DYN (DEPTH*FRAME)   // 70400

// ---------------- device scratch (bss) ----------------
__device__ float g_GI0[(size_t)TT * BB * G3];
__device__ float g_h0f[2][BB * HH];
__device__ float g_h1f[2][BB * HH];
__device__ __nv_bfloat16 g_h0hi[2][BB*HH], g_h0lo[2][BB*HH];
__device__ __nv_bfloat16 g_h1hi[2][BB*HH], g_h1lo[2][BB*HH];
__device__ __nv_bfloat16 g_x1hi[2][BB*HH], g_x1lo[2][BB*HH];
__device__ __nv_bfloat16 g_Whi[3][(size_t)G3*HH];   // 0=Whh0 1=Wih1 2=Whh1
__device__ __nv_bfloat16 g_Wlo[3][(size_t)G3*HH];
__device__ __nv_bfloat16 g_W0hi[(size_t)G3*EE], g_W0lo[(size_t)G3*EE];   // Wih0
__device__ __nv_bfloat16 g_x0hi[(size_t)TT*BB*EE], g_x0lo[(size_t)TT*BB*EE];

// ---------------- helpers ----------------
__device__ __forceinline__ void cpa16(uint32_t dst, const void* src){
    asm volatile("cp.async.cg.shared.global [%0], [%1], 16;" :: "r"(dst), "l"(src));
}
__device__ __forceinline__ void cpa_commit(){ asm volatile("cp.async.commit_group;"); }
__device__ __forceinline__ void cpa_wait3(){ asm volatile("cp.async.wait_group 3;"); }
__device__ __forceinline__ void cpa_wait1(){ asm volatile("cp.async.wait_group 1;"); }

__device__ __forceinline__ void ldsm4(uint32_t* r, uint32_t a){
    asm volatile("ldmatrix.sync.aligned.m8n8.x4.shared.b16 {%0,%1,%2,%3}, [%4];"
        : "=r"(r[0]),"=r"(r[1]),"=r"(r[2]),"=r"(r[3]) : "r"(a));
}

#define MMA16816(c, a, b0, b1) \
    asm volatile("mma.sync.aligned.m16n8k16.row.col.f32.bf16.bf16.f32 " \
        "{%0,%1,%2,%3},{%4,%5,%6,%7},{%8,%9},{%0,%1,%2,%3};" \
        : "+f"((c)[0]),"+f"((c)[1]),"+f"((c)[2]),"+f"((c)[3]) \
        : "r"((a)[0]),"r"((a)[1]),"r"((a)[2]),"r"((a)[3]),"r"(b0),"r"(b1))

__device__ __forceinline__ float sigf(float v){ return 1.f/(1.f+__expf(-v)); }
__device__ __forceinline__ void split2(float v, __nv_bfloat16& hi, __nv_bfloat16& lo){
    hi = __float2bfloat16(v);
    lo = __float2bfloat16(v - __bfloat162float(hi));
}

// ---------------- init kernels ----------------
__global__ void zero_h_kernel() {
    int i = blockIdx.x*256 + threadIdx.x;  // grid 512 -> 131072 = BB*HH
    g_h0f[0][i]=0.f; g_h1f[0][i]=0.f;
    __nv_bfloat16 z = __float2bfloat16(0.f);
    g_h0hi[0][i]=z; g_h0lo[0][i]=z; g_h1hi[0][i]=z; g_h1lo[0][i]=z;
}
__global__ void split_w_kernel(const float* __restrict__ w0, const float* __restrict__ w1,
                               const float* __restrict__ w2) {
    size_t i = (size_t)blockIdx.x*256 + threadIdx.x;
    int m = blockIdx.y;
    const float* s = (m==0)? w0 : (m==1)? w1 : w2;
    __nv_bfloat16 hi, lo; split2(s[i], hi, lo);
    g_Whi[m][i]=hi; g_Wlo[m][i]=lo;
}
__global__ void split_w0_kernel(const float* __restrict__ w) {
    size_t i = (size_t)blockIdx.x*256 + threadIdx.x;   // grid 6144
    __nv_bfloat16 hi, lo; split2(w[i], hi, lo);
    g_W0hi[i]=hi; g_W0lo[i]=lo;
}
__global__ void split_x_kernel(const float* __restrict__ x) {
    size_t i = (size_t)blockIdx.x*256 + threadIdx.x;   // grid 65536
    __nv_bfloat16 hi, lo; split2(x[i], hi, lo);
    g_x0hi[i]=hi; g_x0lo[i]=lo;
}

// ---------------- GI0 via split-bf16 mma ----------------
// grid (48, 512): x = 64-col block of G3 ; y = t*2 + mhalf. CTA = M64 x N64.
__global__ __launch_bounds__(128) void gi0_mma(
    const float* __restrict__ bias, const int* __restrict__ bs)
{
    __shared__ __align__(16) char smem[3*10240];
    const int nbase = blockIdx.x * 64;
    const int trow = blockIdx.y;
    const int t = trow >> 1, mb = (trow & 1) << 6;
    if (mb >= bs[t]) return;
    const int tid = threadIdx.x, wid = tid>>5, lane = tid&31;
    const int l4 = lane>>2, lm4 = lane&3;
    const size_t rowbase = (size_t)(t*BB + mb);

    float cc[8][4];
#pragma unroll
    for (int i=0;i<8;i++)
#pragma unroll
        for (int j=0;j<4;j++) cc[i][j]=0.f;

    const uint32_t smem_u = (uint32_t)__cvta_generic_to_shared(smem);
    const uint32_t a_off = (uint32_t)((wid*16 + (lane&15))*SA + (lane>>4)*16);
    const uint32_t b_off = (uint32_t)(((lane&7) + ((lane>>4)&1)*8)*SA + ((lane>>3)&1)*16);

    auto load_stage = [&](int s){
        const int pass = s >> 4;                     // 16 chunks per pass (K=512)
        const int k0 = (s & 15) * KC;
        const uint32_t st = smem_u + (s % 3) * 10240;
        const __nv_bfloat16* A = (pass==2)? g_x0lo : g_x0hi;
        const __nv_bfloat16* W = (pass==1)? g_W0lo : g_W0hi;
#pragma unroll
        for (int i = 0; i < 2; i++) {                // A: 64 rows x 4 chunks
            int cid = tid + i*128, r = cid>>2, c = cid&3;
            cpa16(st + OFF_A + r*SA + c*16, A + (rowbase+r)*EE + k0 + c*8);
        }
#pragma unroll
        for (int i = 0; i < 2; i++) {                // B: 64 rows x 4 chunks
            int cid = tid + i*128, r = cid>>2, c = cid&3;
            cpa16(st + 5120 + r*SA + c*16, W + (size_t)(nbase+r)*EE + k0 + c*8);
        }
    };

    load_stage(0); cpa_commit();
    load_stage(1); cpa_commit();
    for (int s = 0; s < 48; s++) {
        cpa_wait1();
        __syncthreads();
        const uint32_t st = smem_u + (s % 3) * 10240;
        const uint32_t aB = st + OFF_A + a_off;
        const uint32_t bB = st + 5120 + b_off;
#pragma unroll
        for (int kc = 0; kc < 2; kc++) {
            uint32_t a[4]; ldsm4(a, aB + kc*32);
#pragma unroll
            for (int g = 0; g < 4; g++) {
                uint32_t b[4]; ldsm4(b, bB + g*16*SA + kc*32);
                MMA16816(cc[2*g],   a, b[0], b[1]);
                MMA16816(cc[2*g+1], a, b[2], b[3]);
            }
        }
        __syncthreads();
        if (s+2 < 48) load_stage(s+2);
        cpa_commit();
    }

    // epilogue: write GI0 + bias
#pragma unroll
    for (int nt = 0; nt < 8; nt++) {
        int n = nbase + nt*8 + lm4*2;
        float2 bv = *(const float2*)&bias[n];
#pragma unroll
        for (int rr = 0; rr < 2; rr++) {
            size_t row = rowbase + wid*16 + l4 + rr*8;
            float2 o; o.x = cc[nt][rr*2] + bv.x; o.y = cc[nt][rr*2+1] + bv.y;
            *(float2*)&g_GI0[row*G3 + n] = o;
        }
    }
}

// ---------------- mma.sync fused step (384 CTAs, depth-5 pipeline) ----------------
// CTAs [0,128):   layer0 @ t=kk : M64 x 16 hidden cols (48 gate rows, 6 nt)
// CTAs [128,384): layer1 @ t=kk-1 : M64 x 8 hidden cols, dual GEMMs (3 nt each)
__global__ __launch_bounds__(128, 3) void mma_step(
    const float* __restrict__ bhh0, const float* __restrict__ bih1,
    const float* __restrict__ bhh1, const int* __restrict__ bs, int kk)
{
    extern __shared__ __align__(16) char smem[];
    const int cta = blockIdx.x;
    const bool l1 = cta >= 128;
    const int t = l1 ? kk-1 : kk;
    if (t < 0 || t >= TT) return;
    const int p = t & 1;
    const int idx = l1 ? cta-128 : cta;
    const int jbase = l1 ? (idx>>1)*8 : (idx>>1)*16;
    const int mbase = (idx&1)*64;
    const int tid = threadIdx.x, wid = tid>>5, lane = tid&31;
    const int l4 = lane>>2, lm4 = lane&3;
    const int active = bs[t];
    const int NCOL = l1 ? 8 : 16;
    const int NT = NCOL/8;

    const float* hpf_all = l1 ? g_h1f[p] : g_h0f[p];
    float* hnf_all = l1 ? g_h1f[p^1] : g_h0f[p^1];
    __nv_bfloat16* hhi_all = l1 ? g_h1hi[p^1] : g_h0hi[p^1];
    __nv_bfloat16* hlo_all = l1 ? g_h1lo[p^1] : g_h0lo[p^1];

    if (mbase >= active) {
        const int tot = 64*NCOL;
        for (int i = tid; i < tot; i += 128) {
            int r = i / NCOL, c = i % NCOL;
            size_t off = (size_t)(mbase + r)*HH + jbase + c;
            float hv = hpf_all[off];
            hnf_all[off] = hv;
            __nv_bfloat16 hi, lo; split2(hv, hi, lo);
            hhi_all[off] = hi; hlo_all[off] = lo;
        }
        return;
    }

    // pass base pointers (selected per stage by select-chain, no indexed array)
    const __nv_bfloat16 *AhHi, *AhLo, *WhHi, *WhLo, *AiHi, *AiLo, *WiHi, *WiLo;
    if (!l1) {
        AhHi = g_h0hi[p]; AhLo = g_h0lo[p]; WhHi = g_Whi[0]; WhLo = g_Wlo[0];
        AiHi = AiLo = nullptr; WiHi = WiLo = nullptr;
    } else {
        AhHi = g_h1hi[p]; AhLo = g_h1lo[p]; WhHi = g_Whi[2]; WhLo = g_Wlo[2];
        AiHi = g_x1hi[p]; AiLo = g_x1lo[p]; WiHi = g_Whi[1]; WiLo = g_Wlo[1];
    }

    const uint32_t smem_u = (uint32_t)__cvta_generic_to_shared(smem);

    auto load_stage = [&](int s){
        const int pass = s >> 5;
        const int k0 = (s & 31) * KC;
        const uint32_t st = smem_u + (s % DEPTH) * FRAME;
        const __nv_bfloat16* A  = (pass==2)? AhLo : AhHi;
        const __nv_bfloat16* W  = (pass==1)? WhLo : WhHi;
#pragma unroll
        for (int i = 0; i < 2; i++) {                // A_h: 64 rows x 4 = 256
            int cid = tid + i*128, r = cid>>2, c = cid&3;
            cpa16(st + OFF_A + r*SA + c*16, A + (size_t)(mbase+r)*HH + k0 + c*8);
        }
        if (!l1) {
            // B: 48 rows = 3 gates x 16 cols
#pragma unroll
            for (int i = 0; i < 2; i++) {
                int cid = tid + i*128;
                if (cid < 192) {
                    int r = cid>>2, c = cid&3;
                    int wrow = (r>>4)*HH + jbase + (r&15);
                    cpa16(st + OFF_B + r*SA + c*16, W + (size_t)wrow*HH + k0 + c*8);
                }
            }
        } else {
            const __nv_bfloat16* A2 = (pass==2)? AiLo : AiHi;
            const __nv_bfloat16* W2 = (pass==1)? WiLo : WiHi;
#pragma unroll
            for (int i = 0; i < 2; i++) {            // A_i: 256
                int cid = tid + i*128, r = cid>>2, c = cid&3;
                cpa16(st + OFF_AI + r*SA + c*16, A2 + (size_t)(mbase+r)*HH + k0 + c*8);
            }
            // B packed: rows 0-23 = Wh (3 gates x 8), rows 24-47 = Wi
#pragma unroll
            for (int i = 0; i < 2; i++) {
                int cid = tid + i*128;
                if (cid < 192) {
                    int r = cid>>2, c = cid&3;
                    const __nv_bfloat16* Wp = (r < 24) ? W : W2;
                    int r2 = (r < 24) ? r : r-24;
                    int wrow = (r2>>3)*HH + jbase + (r2&7);
                    cpa16(st + OFF_B + r*SA + c*16, Wp + (size_t)wrow*HH + k0 + c*8);
                }
            }
        }
    };

    float ch[6][4], ci[3][4];
#pragma unroll
    for (int i=0;i<6;i++)
#pragma unroll
        for (int j=0;j<4;j++) ch[i][j]=0.f;
#pragma unroll
    for (int i=0;i<3;i++)
#pragma unroll
        for (int j=0;j<4;j++) ci[i][j]=0.f;

    const uint32_t a_off = (uint32_t)((wid*16 + (lane&15))*SA + (lane>>4)*16);
    const uint32_t b_off = (uint32_t)(((lane&7) + ((lane>>4)&1)*8)*SA + ((lane>>3)&1)*16);

    // depth-5 pipeline, one barrier per stage
#pragma unroll
    for (int i = 0; i < DEPTH-1; i++) { load_stage(i); cpa_commit(); }
    for (int s = 0; s < NSTG; s++) {
        cpa_wait3();
        __syncthreads();
        const uint32_t st = smem_u + (s % DEPTH) * FRAME;
        const uint32_t aH = st + OFF_A + a_off;
        const uint32_t bB = st + OFF_B + b_off;
        if (!l1) {
#pragma unroll
            for (int kc = 0; kc < 2; kc++) {
                uint32_t a[4]; ldsm4(a, aH + kc*32);
#pragma unroll
                for (int g = 0; g < 3; g++) {
                    uint32_t b[4]; ldsm4(b, bB + g*16*SA + kc*32);
                    MMA16816(ch[2*g],   a, b[0], b[1]);
                    MMA16816(ch[2*g+1], a, b[2], b[3]);
                }
            }
        } else {
            const uint32_t aI = st + OFF_AI + a_off;
#pragma unroll
            for (int kc = 0; kc < 2; kc++) {
                uint32_t a[4], ai[4], b[4];
                ldsm4(a,  aH + kc*32);
                ldsm4(ai, aI + kc*32);
                ldsm4(b, bB + 0*16*SA + kc*32);      // Wh gates r,z
                MMA16816(ch[0], a, b[0], b[1]);
                MMA16816(ch[1], a, b[2], b[3]);
                ldsm4(b, bB + 1*16*SA + kc*32);      // Wh gate n | Wi gate r
                MMA16816(ch[2], a,  b[0], b[1]);
                MMA16816(ci[0], ai, b[2], b[3]);
                ldsm4(b, bB + 2*16*SA + kc*32);      // Wi gates z,n
                MMA16816(ci[1], ai, b[0], b[1]);
                MMA16816(ci[2], ai, b[2], b[3]);
            }
        }
        if (s + DEPTH-1 < NSTG) load_stage(s + DEPTH-1);
        cpa_commit();
    }

    // ---- epilogue: gate math + state update (R6-proven) ----
    const int m0 = mbase + wid*16 + l4;
    const float* bh = l1 ? bhh1 : bhh0;
#pragma unroll
    for (int c = 0; c < 2; c++) {
        if (c >= NT) break;
        const int j = jbase + c*8 + lm4*2;
        float2 bhr = *(const float2*)(bh + j);
        float2 bhz = *(const float2*)(bh + HH + j);
        float2 bhn = *(const float2*)(bh + 2*HH + j);
        float2 bir, biz, bin;
        if (l1) {
            bir = *(const float2*)(bih1 + j);
            biz = *(const float2*)(bih1 + HH + j);
            bin = *(const float2*)(bih1 + 2*HH + j);
        }
        const int rg = c, zg = NT + c, ng = 2*NT + c;
#pragma unroll
        for (int rr = 0; rr < 2; rr++) {
            const int m = m0 + rr*8;
            const bool keep = m < active;
            float gr0,gr1,gz0,gz1,gn0,gn1;
            if (!l1) {
                const float* gp = g_GI0 + (size_t)(t*BB + m)*G3;
                float2 a = *(const float2*)(gp + j);
                float2 b = *(const float2*)(gp + HH + j);
                float2 cc2 = *(const float2*)(gp + 2*HH + j);
                gr0=a.x; gr1=a.y; gz0=b.x; gz1=b.y; gn0=cc2.x; gn1=cc2.y;
            } else {
                gr0 = ci[rg][rr*2] + bir.x;  gr1 = ci[rg][rr*2+1] + bir.y;
                gz0 = ci[zg][rr*2] + biz.x;  gz1 = ci[zg][rr*2+1] + biz.y;
                gn0 = ci[ng][rr*2] + bin.x;  gn1 = ci[ng][rr*2+1] + bin.y;
            }
            float hr0 = ch[rg][rr*2] + bhr.x, hr1 = ch[rg][rr*2+1] + bhr.y;
            float hz0 = ch[zg][rr*2] + bhz.x, hz1 = ch[zg][rr*2+1] + bhz.y;
            float hn0 = ch[ng][rr*2] + bhn.x, hn1 = ch[ng][rr*2+1] + bhn.y;

            size_t off = (size_t)m*HH + j;
            float2 hp = *(const float2*)(hpf_all + off);

            float r0 = sigf(gr0+hr0), z0 = sigf(gz0+hz0);
            float nv0 = tanhf(fmaf(r0, hn0, gn0));
            float hv0 = fmaf(z0, hp.x - nv0, nv0);
            float r1 = sigf(gr1+hr1), z1 = sigf(gz1+hz1);
            float nv1 = tanhf(fmaf(r1, hn1, gn1));
            float hv1 = fmaf(z1, hp.y - nv1, nv1);

            float kv0 = keep ? hv0 : hp.x;
            float kv1 = keep ? hv1 : hp.y;

            float2 outv; outv.x = kv0; outv.y = kv1;
            *(float2*)(hnf_all + off) = outv;
            __nv_bfloat162 vhi, vlo;
            split2(kv0, vhi.x, vlo.x);
            split2(kv1, vhi.y, vlo.y);
            *(__nv_bfloat162*)(hhi_all + off) = vhi;
            *(__nv_bfloat162*)(hlo_all + off) = vlo;
            if (!l1) {
                __nv_bfloat162 xh, xl;
                split2(hv0, xh.x, xl.x);
                split2(hv1, xh.y, xl.y);
                *(__nv_bfloat162*)(g_x1hi[p] + off) = xh;
                *(__nv_bfloat162*)(g_x1lo[p] + off) = xl;
            }
        }
    }
}

// ---------------- final gather ----------------
__global__ void gather_kernel(const int* __restrict__ u, float* __restrict__ out) {
    int idx = blockIdx.x*blockDim.x + threadIdx.x;
    int l = idx / (BB*(HH/4));
    int rem = idx % (BB*(HH/4));
    int b = rem / (HH/4), j4 = rem % (HH/4);
    const float* src = (l ? g_h1f[0] : g_h0f[0]) + (size_t)u[b]*HH;
    ((float4*)out)[idx] = ((const float4*)src)[j4];
}

// ---------------------------------------------------------------------------
extern "C" void kernel_launch(void* const* d_in, const int* in_sizes, int n_in,
                              void* d_out, int out_size) {
    const float* x    = (const float*)d_in[0];
    const float* Wih0 = (const float*)d_in[1];
    const float* Whh0 = (const float*)d_in[2];
    const float* bih0 = (const float*)d_in[3];
    const float* bhh0 = (const float*)d_in[4];
    const float* Wih1 = (const float*)d_in[5];
    const float* Whh1 = (const float*)d_in[6];
    const float* bih1 = (const float*)d_in[7];
    const float* bhh1 = (const float*)d_in[8];
    const int*   bs   = (const int*)d_in[9];
    const int*   ui   = (const int*)d_in[10];

    cudaFuncSetAttribute(mma_step, cudaFuncAttributeMaxDynamicSharedMemorySize, SMEM_DYN);

    zero_h_kernel<<<512, 256>>>();
    split_w_kernel<<<dim3((G3*HH)/256, 3), 256>>>(Whh0, Wih1, Whh1);
    split_w0_kernel<<<(G3*EE)/256, 256>>>(Wih0);
    split_x_kernel<<<(TT*BB*EE)/256, 256>>>(x);
    gi0_mma<<<dim3(48, 2*TT), 128>>>(bih0, bs);
    for (int k = 0; k <= TT; k++)
        mma_step<<<384, 128, SMEM_DYN>>>(bhh0, bih1, bhh1, bs, k);
    gather_kernel<<<256, 256>>>(ui, (float*)d_out);
}

// round 9
// speedup vs baseline: 2.0330x; 1.4869x over previous
#include <cuda_runtime.h>
#include <cuda_bf16.h>
#include <stdint.h>
#include <math.h>

#define TT 256
#define BB 128
#define EE 512
#define HH 1024
#define G3 3072
#define KC 32            // K per stage
#define NSTG 32          // single fused sweep over K=1024
#define SA 80            // smem row stride bytes (32 bf16 = 64B + 16B pad)

// per-stage frame (bytes). l1 layout; l0 overlays a subset.
//  l1: AHhi 0, AHlo 5120, AIhi 10240, AIlo 15360, B tiles @20480 (4 x 3840)
//  l0: Ahi 0,  Alo 5120,  Bhi 10240 (7680), Blo 17920 (7680)
#define FRAME  35840
#define DEPTH  3
#define SMEM_DYN (DEPTH*FRAME)   // 107520

// ---------------- device scratch (bss) ----------------
__device__ float g_GI0[(size_t)TT * BB * G3];
__device__ float g_h0f[2][BB * HH];
__device__ float g_h1f[2][BB * HH];
__device__ __nv_bfloat16 g_h0hi[2][BB*HH], g_h0lo[2][BB*HH];
__device__ __nv_bfloat16 g_h1hi[2][BB*HH], g_h1lo[2][BB*HH];
__device__ __nv_bfloat16 g_x1hi[2][BB*HH], g_x1lo[2][BB*HH];
__device__ __nv_bfloat16 g_Whi[3][(size_t)G3*HH];   // 0=Whh0 1=Wih1 2=Whh1
__device__ __nv_bfloat16 g_Wlo[3][(size_t)G3*HH];
__device__ __nv_bfloat16 g_W0hi[(size_t)G3*EE], g_W0lo[(size_t)G3*EE];   // Wih0
__device__ __nv_bfloat16 g_x0hi[(size_t)TT*BB*EE], g_x0lo[(size_t)TT*BB*EE];

// ---------------- helpers ----------------
__device__ __forceinline__ void cpa16(uint32_t dst, const void* src){
    asm volatile("cp.async.cg.shared.global [%0], [%1], 16;" :: "r"(dst), "l"(src));
}
__device__ __forceinline__ void cpa_commit(){ asm volatile("cp.async.commit_group;"); }
__device__ __forceinline__ void cpa_wait1(){ asm volatile("cp.async.wait_group 1;"); }

__device__ __forceinline__ void ldsm4(uint32_t* r, uint32_t a){
    asm volatile("ldmatrix.sync.aligned.m8n8.x4.shared.b16 {%0,%1,%2,%3}, [%4];"
        : "=r"(r[0]),"=r"(r[1]),"=r"(r[2]),"=r"(r[3]) : "r"(a));
}

#define MMA16816(c, a, b0, b1) \
    asm volatile("mma.sync.aligned.m16n8k16.row.col.f32.bf16.bf16.f32 " \
        "{%0,%1,%2,%3},{%4,%5,%6,%7},{%8,%9},{%0,%1,%2,%3};" \
        : "+f"((c)[0]),"+f"((c)[1]),"+f"((c)[2]),"+f"((c)[3]) \
        : "r"((a)[0]),"r"((a)[1]),"r"((a)[2]),"r"((a)[3]),"r"(b0),"r"(b1))

__device__ __forceinline__ float sigf(float v){ return 1.f/(1.f+__expf(-v)); }
__device__ __forceinline__ void split2(float v, __nv_bfloat16& hi, __nv_bfloat16& lo){
    hi = __float2bfloat16(v);
    lo = __float2bfloat16(v - __bfloat162float(hi));
}

// ---------------- init kernels ----------------
__global__ void zero_h_kernel() {
    int i = blockIdx.x*256 + threadIdx.x;  // grid 512 -> 131072 = BB*HH
    g_h0f[0][i]=0.f; g_h1f[0][i]=0.f;
    __nv_bfloat16 z = __float2bfloat16(0.f);
    g_h0hi[0][i]=z; g_h0lo[0][i]=z; g_h1hi[0][i]=z; g_h1lo[0][i]=z;
}
__global__ void split_w_kernel(const float* __restrict__ w0, const float* __restrict__ w1,
                               const float* __restrict__ w2) {
    size_t i = (size_t)blockIdx.x*256 + threadIdx.x;
    int m = blockIdx.y;
    const float* s = (m==0)? w0 : (m==1)? w1 : w2;
    __nv_bfloat16 hi, lo; split2(s[i], hi, lo);
    g_Whi[m][i]=hi; g_Wlo[m][i]=lo;
}
__global__ void split_w0_kernel(const float* __restrict__ w) {
    size_t i = (size_t)blockIdx.x*256 + threadIdx.x;   // grid 6144
    __nv_bfloat16 hi, lo; split2(w[i], hi, lo);
    g_W0hi[i]=hi; g_W0lo[i]=lo;
}
__global__ void split_x_kernel(const float* __restrict__ x) {
    size_t i = (size_t)blockIdx.x*256 + threadIdx.x;   // grid 65536
    __nv_bfloat16 hi, lo; split2(x[i], hi, lo);
    g_x0hi[i]=hi; g_x0lo[i]=lo;
}

// ---------------- GI0 via split-bf16 mma (R8-proven) ----------------
__global__ __launch_bounds__(128) void gi0_mma(
    const float* __restrict__ bias, const int* __restrict__ bs)
{
    __shared__ __align__(16) char smem[3*10240];
    const int nbase = blockIdx.x * 64;
    const int trow = blockIdx.y;
    const int t = trow >> 1, mb = (trow & 1) << 6;
    if (mb >= bs[t]) return;
    const int tid = threadIdx.x, wid = tid>>5, lane = tid&31;
    const int l4 = lane>>2, lm4 = lane&3;
    const size_t rowbase = (size_t)(t*BB + mb);

    float cc[8][4];
#pragma unroll
    for (int i=0;i<8;i++)
#pragma unroll
        for (int j=0;j<4;j++) cc[i][j]=0.f;

    const uint32_t smem_u = (uint32_t)__cvta_generic_to_shared(smem);
    const uint32_t a_off = (uint32_t)((wid*16 + (lane&15))*SA + (lane>>4)*16);
    const uint32_t b_off = (uint32_t)(((lane&7) + ((lane>>4)&1)*8)*SA + ((lane>>3)&1)*16);

    auto load_stage = [&](int s){
        const int pass = s >> 4;
        const int k0 = (s & 15) * KC;
        const uint32_t st = smem_u + (s % 3) * 10240;
        const __nv_bfloat16* A = (pass==2)? g_x0lo : g_x0hi;
        const __nv_bfloat16* W = (pass==1)? g_W0lo : g_W0hi;
#pragma unroll
        for (int i = 0; i < 2; i++) {
            int cid = tid + i*128, r = cid>>2, c = cid&3;
            cpa16(st + r*SA + c*16, A + (rowbase+r)*EE + k0 + c*8);
        }
#pragma unroll
        for (int i = 0; i < 2; i++) {
            int cid = tid + i*128, r = cid>>2, c = cid&3;
            cpa16(st + 5120 + r*SA + c*16, W + (size_t)(nbase+r)*EE + k0 + c*8);
        }
    };

    load_stage(0); cpa_commit();
    load_stage(1); cpa_commit();
    for (int s = 0; s < 48; s++) {
        cpa_wait1();
        __syncthreads();
        const uint32_t st = smem_u + (s % 3) * 10240;
        const uint32_t aB = st + a_off;
        const uint32_t bB = st + 5120 + b_off;
#pragma unroll
        for (int kc = 0; kc < 2; kc++) {
            uint32_t a[4]; ldsm4(a, aB + kc*32);
#pragma unroll
            for (int g = 0; g < 4; g++) {
                uint32_t b[4]; ldsm4(b, bB + g*16*SA + kc*32);
                MMA16816(cc[2*g],   a, b[0], b[1]);
                MMA16816(cc[2*g+1], a, b[2], b[3]);
            }
        }
        __syncthreads();
        if (s+2 < 48) load_stage(s+2);
        cpa_commit();
    }

#pragma unroll
    for (int nt = 0; nt < 8; nt++) {
        int n = nbase + nt*8 + lm4*2;
        float2 bv = *(const float2*)&bias[n];
#pragma unroll
        for (int rr = 0; rr < 2; rr++) {
            size_t row = rowbase + wid*16 + l4 + rr*8;
            float2 o; o.x = cc[nt][rr*2] + bv.x; o.y = cc[nt][rr*2+1] + bv.y;
            *(float2*)&g_GI0[row*G3 + n] = o;
        }
    }
}

// ---------------- fused-pass mma step (192 CTAs x 256 thr) ----------------
// CTAs [0,64):   layer0 @ t=kk : M64 x 32 hidden cols
// CTAs [64,192): layer1 @ t=kk-1 : M64 x 16 hidden cols, dual GEMM (gi/gh split by warp)
__global__ __launch_bounds__(256, 2) void mma_step(
    const float* __restrict__ bhh0, const float* __restrict__ bih1,
    const float* __restrict__ bhh1, const int* __restrict__ bs, int kk)
{
    extern __shared__ __align__(16) char smem[];
    const int cta = blockIdx.x;
    const bool l1 = cta >= 64;
    const int t = l1 ? kk-1 : kk;
    if (t < 0 || t >= TT) return;
    const int p = t & 1;
    const int idx = l1 ? cta-64 : cta;
    const int jbase = l1 ? (idx>>1)*16 : (idx>>1)*32;
    const int mbase = (idx&1)*64;
    const int tid = threadIdx.x, wid = tid>>5, lane = tid&31;
    const int l4 = lane>>2, lm4 = lane&3;
    const int mi = wid & 3;
    const int ws = wid >> 2;            // l0: n-half ; l1: gemm select (0=gh,1=gi)
    const int active = bs[t];
    const int NCOL = l1 ? 16 : 32;

    const float* hpf_all = l1 ? g_h1f[p] : g_h0f[p];
    float* hnf_all = l1 ? g_h1f[p^1] : g_h0f[p^1];
    __nv_bfloat16* hhi_all = l1 ? g_h1hi[p^1] : g_h0hi[p^1];
    __nv_bfloat16* hlo_all = l1 ? g_h1lo[p^1] : g_h0lo[p^1];

    if (mbase >= active) {
        const int tot = 64*NCOL;
        for (int i = tid; i < tot; i += 256) {
            int r = i / NCOL, c = i % NCOL;
            size_t off = (size_t)(mbase + r)*HH + jbase + c;
            float hv = hpf_all[off];
            hnf_all[off] = hv;
            __nv_bfloat16 hi, lo; split2(hv, hi, lo);
            hhi_all[off] = hi; hlo_all[off] = lo;
        }
        return;
    }

    const __nv_bfloat16 *AhHi, *AhLo, *WhHi, *WhLo, *AiHi, *AiLo, *WiHi, *WiLo;
    if (!l1) {
        AhHi = g_h0hi[p]; AhLo = g_h0lo[p]; WhHi = g_Whi[0]; WhLo = g_Wlo[0];
        AiHi = AiLo = WiHi = WiLo = nullptr;
    } else {
        AhHi = g_h1hi[p]; AhLo = g_h1lo[p]; WhHi = g_Whi[2]; WhLo = g_Wlo[2];
        AiHi = g_x1hi[p]; AiLo = g_x1lo[p]; WiHi = g_Whi[1]; WiLo = g_Wlo[1];
    }

    const uint32_t smem_u = (uint32_t)__cvta_generic_to_shared(smem);

    auto load_stage = [&](int s){
        const int k0 = s * KC;
        const uint32_t st = smem_u + (s % DEPTH) * FRAME;
        if (!l1) {
            // A: 2 tiles (hi,lo) x 256 ops
#pragma unroll
            for (int i = 0; i < 2; i++) {
                int cid = tid + i*256, tile = cid>>8, rr = cid&255;
                int r = rr>>2, c = rr&3;
                const __nv_bfloat16* A = tile ? AhLo : AhHi;
                cpa16(st + tile*5120 + r*SA + c*16, A + (size_t)(mbase+r)*HH + k0 + c*8);
            }
            // B: 2 tiles (hi,lo) x 384 ops (96 rows: gate*32+col)
#pragma unroll
            for (int i = 0; i < 3; i++) {
                int cid = tid + i*256, tile = cid/384, rr = cid%384;
                int r = rr>>2, c = rr&3;
                int wrow = (r>>5)*HH + jbase + (r&31);
                const __nv_bfloat16* W = tile ? WhLo : WhHi;
                cpa16(st + 10240 + tile*7680 + r*SA + c*16, W + (size_t)wrow*HH + k0 + c*8);
            }
        } else {
            // A: 4 tiles (AHhi,AHlo,AIhi,AIlo) x 256 ops
#pragma unroll
            for (int i = 0; i < 4; i++) {
                int cid = tid + i*256, tile = cid>>8, rr = cid&255;
                int r = rr>>2, c = rr&3;
                const __nv_bfloat16* A = (tile==0)? AhHi : (tile==1)? AhLo
                                       : (tile==2)? AiHi : AiLo;
                cpa16(st + tile*5120 + r*SA + c*16, A + (size_t)(mbase+r)*HH + k0 + c*8);
            }
            // B: 4 tiles (WHhi,WHlo,WIhi,WIlo) x 192 ops (48 rows: gate*16+col)
#pragma unroll
            for (int i = 0; i < 3; i++) {
                int cid = tid + i*256, tile = cid/192, rr = cid%192;
                int r = rr>>2, c = rr&3;
                int wrow = (r>>4)*HH + jbase + (r&15);
                const __nv_bfloat16* W = (tile==0)? WhHi : (tile==1)? WhLo
                                       : (tile==2)? WiHi : WiLo;
                cpa16(st + 20480 + tile*3840 + r*SA + c*16, W + (size_t)wrow*HH + k0 + c*8);
            }
        }
    };

    float acc[6][4];
#pragma unroll
    for (int i=0;i<6;i++)
#pragma unroll
        for (int j=0;j<4;j++) acc[i][j]=0.f;

    const uint32_t a_off = (uint32_t)((mi*16 + (lane&15))*SA + (lane>>4)*16);
    const uint32_t b_off = (uint32_t)(((lane&7) + ((lane>>4)&1)*8)*SA + ((lane>>3)&1)*16);

    load_stage(0); cpa_commit();
    load_stage(1); cpa_commit();
    for (int s = 0; s < NSTG; s++) {
        cpa_wait1();
        __syncthreads();
        const uint32_t st = smem_u + (s % DEPTH) * FRAME;
        if (!l1) {
            const uint32_t aH = st + a_off;            // hi
            const uint32_t aL = st + 5120 + a_off;     // lo
            const uint32_t grp = (uint32_t)(ws*16*SA); // n-half offset within gate group
#pragma unroll
            for (int kc = 0; kc < 2; kc++) {
                uint32_t ah[4], al[4];
                ldsm4(ah, aH + kc*32);
                ldsm4(al, aL + kc*32);
#pragma unroll
                for (int g = 0; g < 3; g++) {
                    uint32_t bh[4], bl[4];
                    uint32_t bgo = (uint32_t)(g*32*SA) + grp + b_off + kc*32;
                    ldsm4(bh, st + 10240 + bgo);
                    ldsm4(bl, st + 17920 + bgo);
                    MMA16816(acc[2*g],   ah, bh[0], bh[1]);
                    MMA16816(acc[2*g+1], ah, bh[2], bh[3]);
                    MMA16816(acc[2*g],   ah, bl[0], bl[1]);
                    MMA16816(acc[2*g+1], ah, bl[2], bl[3]);
                    MMA16816(acc[2*g],   al, bh[0], bh[1]);
                    MMA16816(acc[2*g+1], al, bh[2], bh[3]);
                }
            }
        } else {
            const uint32_t aH = st + (ws?10240:0) + a_off;         // hi (AH or AI)
            const uint32_t aL = aH + 5120;                         // lo
            const uint32_t bHbase = st + 20480 + (ws?7680:0);      // hi tile (WH or WI)
#pragma unroll
            for (int kc = 0; kc < 2; kc++) {
                uint32_t ah[4], al[4];
                ldsm4(ah, aH + kc*32);
                ldsm4(al, aL + kc*32);
#pragma unroll
                for (int g = 0; g < 3; g++) {
                    uint32_t bh[4], bl[4];
                    uint32_t bgo = (uint32_t)(g*16*SA) + b_off + kc*32;
                    ldsm4(bh, bHbase + bgo);
                    ldsm4(bl, bHbase + 3840 + bgo);
                    MMA16816(acc[2*g],   ah, bh[0], bh[1]);
                    MMA16816(acc[2*g+1], ah, bh[2], bh[3]);
                    MMA16816(acc[2*g],   ah, bl[0], bl[1]);
                    MMA16816(acc[2*g+1], ah, bl[2], bl[3]);
                    MMA16816(acc[2*g],   al, bh[0], bh[1]);
                    MMA16816(acc[2*g+1], al, bh[2], bh[3]);
                }
            }
        }
        if (s+2 < NSTG) load_stage(s+2);
        cpa_commit();
    }

    // ---- l1: exchange gi accumulators to gh warps via smem ----
    float ci[6][4];
    if (l1) {
        float* xch = (float*)smem;
        if (ws == 1) {
            float* dst = xch + (size_t)(mi*32 + lane)*24;
#pragma unroll
            for (int i = 0; i < 6; i++)
#pragma unroll
                for (int j = 0; j < 4; j++) dst[i*4+j] = acc[i][j];
        }
        __syncthreads();
        if (ws == 0) {
            const float* src = xch + (size_t)(mi*32 + lane)*24;
#pragma unroll
            for (int i = 0; i < 6; i++)
#pragma unroll
                for (int j = 0; j < 4; j++) ci[i][j] = src[i*4+j];
        } else {
            return;   // gi warps done
        }
    }

    // ---- epilogue (R8-proven gate math) ----
    const int m0 = mbase + mi*16 + l4;
    const int jw = l1 ? jbase : (jbase + ws*16);
    const float* bh = l1 ? bhh1 : bhh0;
#pragma unroll
    for (int c = 0; c < 2; c++) {
        const int j = jw + c*8 + lm4*2;
        float2 bhr = *(const float2*)(bh + j);
        float2 bhz = *(const float2*)(bh + HH + j);
        float2 bhn = *(const float2*)(bh + 2*HH + j);
        float2 bir, biz, bin;
        if (l1) {
            bir = *(const float2*)(bih1 + j);
            biz = *(const float2*)(bih1 + HH + j);
            bin = *(const float2*)(bih1 + 2*HH + j);
        }
        const int rg = c, zg = 2 + c, ng = 4 + c;   // acc idx = gate*2 + c
#pragma unroll
        for (int rr = 0; rr < 2; rr++) {
            const int m = m0 + rr*8;
            const bool keep = m < active;
            float gr0,gr1,gz0,gz1,gn0,gn1;
            if (!l1) {
                const float* gp = g_GI0 + (size_t)(t*BB + m)*G3;
                float2 a = *(const float2*)(gp + j);
                float2 b = *(const float2*)(gp + HH + j);
                float2 cc2 = *(const float2*)(gp + 2*HH + j);
                gr0=a.x; gr1=a.y; gz0=b.x; gz1=b.y; gn0=cc2.x; gn1=cc2.y;
            } else {
                gr0 = ci[rg][rr*2] + bir.x;  gr1 = ci[rg][rr*2+1] + bir.y;
                gz0 = ci[zg][rr*2] + biz.x;  gz1 = ci[zg][rr*2+1] + biz.y;
                gn0 = ci[ng][rr*2] + bin.x;  gn1 = ci[ng][rr*2+1] + bin.y;
            }
            float hr0 = acc[rg][rr*2] + bhr.x, hr1 = acc[rg][rr*2+1] + bhr.y;
            float hz0 = acc[zg][rr*2] + bhz.x, hz1 = acc[zg][rr*2+1] + bhz.y;
            float hn0 = acc[ng][rr*2] + bhn.x, hn1 = acc[ng][rr*2+1] + bhn.y;

            size_t off = (size_t)m*HH + j;
            float2 hp = *(const float2*)(hpf_all + off);

            float r0 = sigf(gr0+hr0), z0 = sigf(gz0+hz0);
            float nv0 = tanhf(fmaf(r0, hn0, gn0));
            float hv0 = fmaf(z0, hp.x - nv0, nv0);
            float r1 = sigf(gr1+hr1), z1 = sigf(gz1+hz1);
            float nv1 = tanhf(fmaf(r1, hn1, gn1));
            float hv1 = fmaf(z1, hp.y - nv1, nv1);

            float kv0 = keep ? hv0 : hp.x;
            float kv1 = keep ? hv1 : hp.y;

            float2 outv; outv.x = kv0; outv.y = kv1;
            *(float2*)(hnf_all + off) = outv;
            __nv_bfloat162 vhi, vlo;
            split2(kv0, vhi.x, vlo.x);
            split2(kv1, vhi.y, vlo.y);
            *(__nv_bfloat162*)(hhi_all + off) = vhi;
            *(__nv_bfloat162*)(hlo_all + off) = vlo;
            if (!l1) {
                __nv_bfloat162 xh, xl;
                split2(hv0, xh.x, xl.x);
                split2(hv1, xh.y, xl.y);
                *(__nv_bfloat162*)(g_x1hi[p] + off) = xh;
                *(__nv_bfloat162*)(g_x1lo[p] + off) = xl;
            }
        }
    }
}

// ---------------- final gather ----------------
__global__ void gather_kernel(const int* __restrict__ u, float* __restrict__ out) {
    int idx = blockIdx.x*blockDim.x + threadIdx.x;
    int l = idx / (BB*(HH/4));
    int rem = idx % (BB*(HH/4));
    int b = rem / (HH/4), j4 = rem % (HH/4);
    const float* src = (l ? g_h1f[0] : g_h0f[0]) + (size_t)u[b]*HH;
    ((float4*)out)[idx] = ((const float4*)src)[j4];
}

// ---------------------------------------------------------------------------
extern "C" void kernel_launch(void* const* d_in, const int* in_sizes, int n_in,
                              void* d_out, int out_size) {
    const float* x    = (const float*)d_in[0];
    const float* Wih0 = (const float*)d_in[1];
    const float* Whh0 = (const float*)d_in[2];
    const float* bih0 = (const float*)d_in[3];
    const float* bhh0 = (const float*)d_in[4];
    const float* Wih1 = (const float*)d_in[5];
    const float* Whh1 = (const float*)d_in[6];
    const float* bih1 = (const float*)d_in[7];
    const float* bhh1 = (const float*)d_in[8];
    const int*   bs   = (const int*)d_in[9];
    const int*   ui   = (const int*)d_in[10];

    cudaFuncSetAttribute(mma_step, cudaFuncAttributeMaxDynamicSharedMemorySize, SMEM_DYN);

    zero_h_kernel<<<512, 256>>>();
    split_w_kernel<<<dim3((G3*HH)/256, 3), 256>>>(Whh0, Wih1, Whh1);
    split_w0_kernel<<<(G3*EE)/256, 256>>>(Wih0);
    split_x_kernel<<<(TT*BB*EE)/256, 256>>>(x);
    gi0_mma<<<dim3(48, 2*TT), 128>>>(bih0, bs);
    for (int k = 0; k <= TT; k++)
        mma_step<<<192, 256, SMEM_DYN>>>(bhh0, bih1, bhh1, bs, k);
    gather_kernel<<<256, 256>>>(ui, (float*)d_out);
}